// round 1
// baseline (speedup 1.0000x reference)
#include <cuda_runtime.h>
#include <math.h>

#define B_IMG   64
#define CH      8
#define NF      64
#define NPIX    1024            // 32*32
#define NSTATE  (B_IMG*CH*NPIX)     // 524288
#define NHID    (B_IMG*NF*NPIX)     // 4194304
#define N_STEPS 24

// ---------------- device state ----------------
__device__ float g_y[NSTATE];
__device__ float g_y5[NSTATE];
__device__ float g_k[7][NSTATE];
__device__ float g_h1[NHID];
__device__ float g_h2[NHID];
__device__ float g_t, g_dt;
__device__ float g_partial[512];
__device__ int   g_accept;

// ---------------- dopri5 tableau ----------------
__constant__ float c_toff[7] = {0.f, 0.2f, 0.3f, 0.8f, (float)(8.0/9.0), 1.f, 1.f};
__constant__ float c_coef[7][6] = {
  {0,0,0,0,0,0},
  {0.2f,0,0,0,0,0},
  {(float)(3.0/40.0),(float)(9.0/40.0),0,0,0,0},
  {(float)(44.0/45.0),(float)(-56.0/15.0),(float)(32.0/9.0),0,0,0},
  {(float)(19372.0/6561.0),(float)(-25360.0/2187.0),(float)(64448.0/6561.0),(float)(-212.0/729.0),0,0},
  {(float)(9017.0/3168.0),(float)(-355.0/33.0),(float)(46732.0/5247.0),(float)(49.0/176.0),(float)(-5103.0/18656.0),0},
  {(float)(35.0/384.0),0.f,(float)(500.0/1113.0),(float)(125.0/192.0),(float)(-2187.0/6784.0),(float)(11.0/84.0)}
};
#define E1f ((float)(71.0/57600.0))
#define E3f ((float)(-71.0/16695.0))
#define E4f ((float)(71.0/1920.0))
#define E5f ((float)(-17253.0/339200.0))
#define E6f ((float)(22.0/525.0))
#define E7f ((float)(-1.0/40.0))

// ---------------- init: y0 = concat(x, zeros) ----------------
__global__ void init_kernel(const float* __restrict__ x) {
  int i = blockIdx.x * 256 + threadIdx.x;
  if (i == 0) { g_t = 0.f; g_dt = 0.1f; g_accept = 0; }
  if (i < NSTATE) {
    int p = i & 1023;
    int c = (i >> 10) & 7;
    int b = i >> 13;
    g_y[i] = (c < 3) ? x[b*3*NPIX + c*NPIX + p] : 0.f;
  }
}

// ---------------- conv1: stage combine + 1x1 (9->64) + relu ----------------
__global__ __launch_bounds__(256) void conv1_kernel(const float* __restrict__ w1,
                                                    const float* __restrict__ b1,
                                                    int stage) {
  __shared__ float w1s[576];
  __shared__ float bias1[64];
  int tid = threadIdx.x;
  float tcur = g_t;
  float dtc  = fminf(g_dt, 1.f - tcur);
  float teval = tcur + c_toff[stage] * dtc;

  for (int i = tid; i < 576; i += 256) w1s[i] = w1[i];
  __syncthreads();
  if (tid < 64) bias1[tid] = b1[tid] + w1s[tid*9] * teval;   // t channel (c=0)
  __syncthreads();

  int idx = blockIdx.x * 256 + tid;       // b*1024 + p
  int p = idx & 1023;
  int b = idx >> 10;
  int base = (b << 13) + p;               // y element base

  float yt[8];
  #pragma unroll
  for (int c = 0; c < 8; c++) yt[c] = g_y[base + c*1024];

  for (int j = 0; j < stage; j++) {
    float cf = c_coef[stage][j];
    if (cf != 0.f) {
      float a = dtc * cf;
      #pragma unroll
      for (int c = 0; c < 8; c++) yt[c] += a * g_k[j][base + c*1024];
    }
  }
  if (stage == 6) {
    #pragma unroll
    for (int c = 0; c < 8; c++) g_y5[base + c*1024] = yt[c];
  }

  int hbase = b * (NF*NPIX) + p;
  #pragma unroll
  for (int o = 0; o < 64; o++) {
    float acc = bias1[o];
    #pragma unroll
    for (int c = 0; c < 8; c++) acc += w1s[o*9 + 1 + c] * yt[c];
    g_h1[hbase + o*1024] = fmaxf(acc, 0.f);
  }
}

// ---------------- conv2: 3x3 (65->64), pad 1, relu ----------------
__global__ __launch_bounds__(256) void conv2_kernel(const float* __restrict__ w2,
                                                    const float* __restrict__ b2,
                                                    int stage) {
  __shared__ float tile[8*1024];   // 8 input channels, full 32x32 image
  __shared__ float ws[16*8*9];     // 16 och x 8 cin x 9 taps
  __shared__ float w0s[16*9];      // t-channel weights
  __shared__ float b2s[16];

  int tid  = threadIdx.x;
  int bimg = blockIdx.x;
  int obase = blockIdx.y * 16;
  int col  = tid & 31;
  int row0 = tid >> 5;             // rows row0, row0+8, row0+16, row0+24

  float tcur = g_t;
  float dtc  = fminf(g_dt, 1.f - tcur);
  float teval = tcur + c_toff[stage] * dtc;

  for (int i = tid; i < 144; i += 256)
    w0s[i] = w2[(obase + i/9)*585 + (i%9)];
  if (tid < 16) b2s[tid] = b2[obase + tid];
  __syncthreads();

  float acc[4][16];
  #pragma unroll
  for (int px = 0; px < 4; px++)
    #pragma unroll
    for (int o = 0; o < 16; o++) acc[px][o] = 0.f;

  // t-channel contribution (constant channel, zero-padded at borders)
  #pragma unroll
  for (int o = 0; o < 16; o++) {
    float w[9];
    #pragma unroll
    for (int tp = 0; tp < 9; tp++) w[tp] = w0s[o*9 + tp];
    #pragma unroll
    for (int px = 0; px < 4; px++) {
      int r = row0 + px*8;
      #pragma unroll
      for (int kh = -1; kh <= 1; kh++) {
        int rr = r + kh;
        #pragma unroll
        for (int kw = -1; kw <= 1; kw++) {
          int cc2 = col + kw;
          if (rr >= 0 && rr < 32 && cc2 >= 0 && cc2 < 32)
            acc[px][o] += teval * w[(kh+1)*3 + (kw+1)];
        }
      }
    }
  }

  const float* h1b = g_h1 + bimg * (NF*NPIX);
  for (int cc = 0; cc < 8; cc++) {
    __syncthreads();
    for (int i = tid; i < 8192; i += 256) tile[i] = h1b[cc*8192 + i];
    for (int i = tid; i < 1152; i += 256) {
      int o = i / 72; int rest = i % 72; int ci = rest / 9; int tp = rest % 9;
      ws[i] = w2[(obase + o)*585 + (cc*8 + ci + 1)*9 + tp];
    }
    __syncthreads();

    #pragma unroll 1
    for (int ci = 0; ci < 8; ci++) {
      float v[4][9];
      #pragma unroll
      for (int px = 0; px < 4; px++) {
        int r = row0 + px*8;
        #pragma unroll
        for (int kh = -1; kh <= 1; kh++) {
          int rr = r + kh;
          #pragma unroll
          for (int kw = -1; kw <= 1; kw++) {
            int cc2 = col + kw;
            float val = 0.f;
            if (rr >= 0 && rr < 32 && cc2 >= 0 && cc2 < 32)
              val = tile[ci*1024 + rr*32 + cc2];
            v[px][(kh+1)*3 + (kw+1)] = val;
          }
        }
      }
      #pragma unroll
      for (int o = 0; o < 16; o++) {
        float w[9];
        #pragma unroll
        for (int tp = 0; tp < 9; tp++) w[tp] = ws[o*72 + ci*9 + tp];
        #pragma unroll
        for (int px = 0; px < 4; px++)
          #pragma unroll
          for (int tp = 0; tp < 9; tp++)
            acc[px][o] += w[tp] * v[px][tp];
      }
    }
  }

  float* h2b = g_h2 + bimg * (NF*NPIX);
  #pragma unroll
  for (int o = 0; o < 16; o++) {
    #pragma unroll
    for (int px = 0; px < 4; px++) {
      int r = row0 + px*8;
      h2b[(obase + o)*1024 + r*32 + col] = fmaxf(acc[px][o] + b2s[o], 0.f);
    }
  }
}

// ---------------- conv3: 1x1 (65->8), writes k[stage] ----------------
__global__ __launch_bounds__(256) void conv3_kernel(const float* __restrict__ w3,
                                                    const float* __restrict__ b3,
                                                    int stage) {
  __shared__ float w3s[520];
  __shared__ float bias3[8];
  int tid = threadIdx.x;
  float tcur = g_t;
  float dtc  = fminf(g_dt, 1.f - tcur);
  float teval = tcur + c_toff[stage] * dtc;

  for (int i = tid; i < 520; i += 256) w3s[i] = w3[i];
  __syncthreads();
  if (tid < 8) bias3[tid] = b3[tid] + w3s[tid*65] * teval;
  __syncthreads();

  int idx = blockIdx.x * 256 + tid;
  int p = idx & 1023;
  int b = idx >> 10;
  int hbase = b * (NF*NPIX) + p;

  float acc[8];
  #pragma unroll
  for (int o = 0; o < 8; o++) acc[o] = bias3[o];

  #pragma unroll 4
  for (int c = 0; c < 64; c++) {
    float h = g_h2[hbase + c*1024];
    #pragma unroll
    for (int o = 0; o < 8; o++) acc[o] += w3s[o*65 + c + 1] * h;
  }

  int base = (b << 13) + p;
  float* kd = g_k[stage];
  #pragma unroll
  for (int o = 0; o < 8; o++) kd[base + o*1024] = acc[o];
}

// ---------------- error norm: partial sums (deterministic) ----------------
__global__ void err_kernel() {
  int tid = threadIdx.x;
  float dtc = fminf(g_dt, 1.f - g_t);
  float local = 0.f;
  for (int e = blockIdx.x * 256 + tid; e < NSTATE; e += 512*256) {
    float err = dtc * (E1f*g_k[0][e] + E3f*g_k[2][e] + E4f*g_k[3][e] +
                       E5f*g_k[4][e] + E6f*g_k[5][e] + E7f*g_k[6][e]);
    float yv = g_y[e], y5 = g_y5[e];
    float tol = 1e-3f + 1e-3f * fmaxf(fabsf(yv), fabsf(y5));
    float r = err / tol;
    local += r * r;
  }
  __shared__ float red[256];
  red[tid] = local; __syncthreads();
  for (int s = 128; s > 0; s >>= 1) { if (tid < s) red[tid] += red[tid+s]; __syncthreads(); }
  if (tid == 0) g_partial[blockIdx.x] = red[0];
}

// ---------------- step controller ----------------
__global__ void update_kernel() {
  __shared__ float red[256];
  int tid = threadIdx.x;
  red[tid] = g_partial[tid] + g_partial[tid + 256];
  __syncthreads();
  for (int s = 128; s > 0; s >>= 1) { if (tid < s) red[tid] += red[tid+s]; __syncthreads(); }
  if (tid == 0) {
    float err_norm = sqrtf(red[0] * (1.f / (float)NSTATE));
    float tcur = g_t, dt = g_dt;
    float dtc  = fminf(dt, 1.f - tcur);
    bool done = tcur >= 1.f - 1e-7f;
    bool adv  = (err_norm <= 1.f) && (!done);
    g_accept = adv ? 1 : 0;
    g_t = adv ? (tcur + dtc) : tcur;
    float safe = fmaxf(err_norm, 1e-10f);
    float factor = 0.9f * powf(safe, -0.2f);
    factor = fminf(fmaxf(factor, 0.2f), 10.f);
    g_dt = done ? dt : dtc * factor;
  }
}

__global__ void accept_kernel() {
  if (g_accept == 0) return;
  int i = blockIdx.x * 256 + threadIdx.x;
  g_y[i] = g_y5[i];
}

// ---------------- final linear head ----------------
__global__ void head_kernel(const float* __restrict__ wl,
                            const float* __restrict__ bl,
                            float* __restrict__ out) {
  int b = blockIdx.x / 10, o = blockIdx.x % 10;
  int tid = threadIdx.x;
  const float* yb = g_y + b * 8192;
  const float* wo = wl + o * 8192;
  float s = 0.f;
  for (int i = tid; i < 8192; i += 256) s += yb[i] * wo[i];
  __shared__ float red[256];
  red[tid] = s; __syncthreads();
  for (int st = 128; st > 0; st >>= 1) { if (tid < st) red[tid] += red[tid+st]; __syncthreads(); }
  if (tid == 0) out[blockIdx.x] = red[0] + bl[o];
}

// ---------------- launcher ----------------
extern "C" void kernel_launch(void* const* d_in, const int* in_sizes, int n_in,
                              void* d_out, int out_size) {
  const float* x  = (const float*)d_in[0];
  const float* w1 = (const float*)d_in[1];
  const float* b1 = (const float*)d_in[2];
  const float* w2 = (const float*)d_in[3];
  const float* b2 = (const float*)d_in[4];
  const float* w3 = (const float*)d_in[5];
  const float* b3 = (const float*)d_in[6];
  const float* wl = (const float*)d_in[7];
  const float* bl = (const float*)d_in[8];
  float* out = (float*)d_out;

  init_kernel<<<NSTATE/256, 256>>>(x);
  for (int step = 0; step < N_STEPS; step++) {
    for (int s = 0; s < 7; s++) {
      conv1_kernel<<<256, 256>>>(w1, b1, s);
      conv2_kernel<<<dim3(64, 4), 256>>>(w2, b2, s);
      conv3_kernel<<<256, 256>>>(w3, b3, s);
    }
    err_kernel<<<512, 256>>>();
    update_kernel<<<1, 256>>>();
    accept_kernel<<<NSTATE/256, 256>>>();
  }
  head_kernel<<<640, 256>>>(wl, bl, out);
}

// round 2
// speedup vs baseline: 1.1449x; 1.1449x over previous
#include <cuda_runtime.h>
#include <math.h>

#define B_IMG   64
#define CH      8
#define NF      64
#define NPIX    1024
#define NSTATE  (B_IMG*CH*NPIX)     // 524288
#define NHID    (B_IMG*NF*NPIX)     // 4194304
#define N_STEPS 24

typedef unsigned long long ull;

__device__ __forceinline__ ull pack2(float lo, float hi) {
  ull r; asm("mov.b64 %0, {%1, %2};" : "=l"(r) : "f"(lo), "f"(hi)); return r;
}
__device__ __forceinline__ float2 unpk(ull v) {
  float2 f; asm("mov.b64 {%0, %1}, %2;" : "=f"(f.x), "=f"(f.y) : "l"(v)); return f;
}
// d = a*b + d  (packed 2x fp32, bit-exact vs two fmaf)
#define FMA2(d,a,b) asm("fma.rn.f32x2 %0, %1, %2, %0;" : "+l"(d) : "l"(a), "l"(b))

// ---------------- device state ----------------
// y,y5,k : [b][px][c]  (c contiguous, 8 floats)
// h1,h2  : [b][px][och] (64 contiguous)
__device__ float g_y[NSTATE];
__device__ float g_y5[NSTATE];
__device__ float g_k[7][NSTATE];
__device__ float g_h1[NHID];
__device__ float g_h2[NHID];
__device__ float g_t, g_dt;
__device__ float g_partial[512];
__device__ int   g_accept;

__constant__ float c_toff[7] = {0.f, 0.2f, 0.3f, 0.8f, (float)(8.0/9.0), 1.f, 1.f};
__constant__ float c_coef[7][6] = {
  {0,0,0,0,0,0},
  {0.2f,0,0,0,0,0},
  {(float)(3.0/40.0),(float)(9.0/40.0),0,0,0,0},
  {(float)(44.0/45.0),(float)(-56.0/15.0),(float)(32.0/9.0),0,0,0},
  {(float)(19372.0/6561.0),(float)(-25360.0/2187.0),(float)(64448.0/6561.0),(float)(-212.0/729.0),0,0},
  {(float)(9017.0/3168.0),(float)(-355.0/33.0),(float)(46732.0/5247.0),(float)(49.0/176.0),(float)(-5103.0/18656.0),0},
  {(float)(35.0/384.0),0.f,(float)(500.0/1113.0),(float)(125.0/192.0),(float)(-2187.0/6784.0),(float)(11.0/84.0)}
};
#define E1f ((float)(71.0/57600.0))
#define E3f ((float)(-71.0/16695.0))
#define E4f ((float)(71.0/1920.0))
#define E5f ((float)(-17253.0/339200.0))
#define E6f ((float)(22.0/525.0))
#define E7f ((float)(-1.0/40.0))

// ---------------- init ----------------
__global__ void init_kernel(const float* __restrict__ x) {
  int i = blockIdx.x * 256 + threadIdx.x;
  if (i == 0) { g_t = 0.f; g_dt = 0.1f; g_accept = 0; }
  if (i < NSTATE) {
    int c = i & 7;
    int p = (i >> 3) & 1023;
    int b = i >> 13;
    g_y[i] = (c < 3) ? x[b*3*NPIX + c*NPIX + p] : 0.f;
  }
}

// ---------------- conv1: (accept) + stage combine + 1x1 (9->64) + relu ----------------
__global__ __launch_bounds__(256) void conv1_kernel(const float* __restrict__ w1,
                                                    const float* __restrict__ b1,
                                                    int stage) {
  __shared__ __align__(16) ull w1s2[256];  // [c][o2] = c*32+o2
  __shared__ ull bias2[32];
  int tid = threadIdx.x;
  float tcur = g_t;
  float dtc  = fminf(g_dt, 1.f - tcur);
  float teval = tcur + c_toff[stage] * dtc;
  int accf = (stage == 0) ? g_accept : 0;

  {
    int c = tid >> 5, o2 = tid & 31;
    w1s2[tid] = pack2(w1[(2*o2)*9 + 1 + c], w1[(2*o2+1)*9 + 1 + c]);
  }
  if (tid < 32)
    bias2[tid] = pack2(b1[2*tid]   + w1[(2*tid)*9]   * teval,
                       b1[2*tid+1] + w1[(2*tid+1)*9] * teval);
  __syncthreads();

  int idx = blockIdx.x * 256 + tid;   // b*1024 + px
  const float4* ysrc = (const float4*)(accf ? g_y5 : g_y);
  float4 ya = ysrc[idx*2], yb = ysrc[idx*2+1];
  if (accf) { ((float4*)g_y)[idx*2] = ya; ((float4*)g_y)[idx*2+1] = yb; }

  float yt[8] = {ya.x, ya.y, ya.z, ya.w, yb.x, yb.y, yb.z, yb.w};
  for (int j = 0; j < stage; j++) {
    float cf = c_coef[stage][j];
    if (cf != 0.f) {
      float a = dtc * cf;
      const float4* kj = (const float4*)g_k[j];
      float4 k0 = kj[idx*2], k1 = kj[idx*2+1];
      yt[0] += a*k0.x; yt[1] += a*k0.y; yt[2] += a*k0.z; yt[3] += a*k0.w;
      yt[4] += a*k1.x; yt[5] += a*k1.y; yt[6] += a*k1.z; yt[7] += a*k1.w;
    }
  }
  if (stage == 6) {
    float4* y5p = (float4*)g_y5;
    y5p[idx*2]   = make_float4(yt[0], yt[1], yt[2], yt[3]);
    y5p[idx*2+1] = make_float4(yt[4], yt[5], yt[6], yt[7]);
  }

  ull yy[8];
  #pragma unroll
  for (int c = 0; c < 8; c++) yy[c] = pack2(yt[c], yt[c]);

  float4* dst = (float4*)(g_h1 + (size_t)idx * 64);
  #pragma unroll
  for (int o4 = 0; o4 < 16; o4++) {
    ull a0 = bias2[2*o4], a1 = bias2[2*o4+1];
    #pragma unroll
    for (int c = 0; c < 8; c++) {
      FMA2(a0, yy[c], w1s2[c*32 + 2*o4]);
      FMA2(a1, yy[c], w1s2[c*32 + 2*o4 + 1]);
    }
    float2 f0 = unpk(a0), f1 = unpk(a1);
    float4 s;
    s.x = fmaxf(f0.x, 0.f); s.y = fmaxf(f0.y, 0.f);
    s.z = fmaxf(f1.x, 0.f); s.w = fmaxf(f1.y, 0.f);
    dst[o4] = s;
  }
}

// ---------------- conv2: 3x3 (65->64), pad 1, relu ----------------
__global__ __launch_bounds__(256) void conv2_kernel(const float* __restrict__ w2,
                                                    const float* __restrict__ b2,
                                                    int stage) {
  __shared__ float tile[8*1156];            // 8 ci planes, padded 34x34
  __shared__ __align__(16) ull ws2[576];    // [ci][tp][o2] = (ci*9+tp)*8+o2
  __shared__ ull w0s2[72];                  // t-channel: [tp][o2]
  __shared__ float b2s[16];

  int tid  = threadIdx.x;
  int bimg = blockIdx.x;
  int obase = blockIdx.y * 16;
  int col  = tid & 31;
  int row0 = tid >> 5;

  float tcur = g_t;
  float dtc  = fminf(g_dt, 1.f - tcur);
  float teval = tcur + c_toff[stage] * dtc;

  for (int i = tid; i < 8*1156; i += 256) tile[i] = 0.f;
  if (tid < 72) {
    int tp = tid >> 3, o2 = tid & 7;
    w0s2[tid] = pack2(w2[(obase+2*o2)*585 + tp], w2[(obase+2*o2+1)*585 + tp]);
  }
  if (tid < 16) b2s[tid] = b2[obase + tid];
  __syncthreads();

  ull acc[4][8];
  #pragma unroll
  for (int px = 0; px < 4; px++)
    #pragma unroll
    for (int o2 = 0; o2 < 8; o2++) acc[px][o2] = 0ULL;

  // t-channel (constant value, zero-padded borders)
  #pragma unroll
  for (int px = 0; px < 4; px++) {
    int r = row0 + px*8;
    #pragma unroll
    for (int kh = -1; kh <= 1; kh++) {
      int rr = r + kh; bool rok = (rr >= 0) && (rr < 32);
      #pragma unroll
      for (int kw = -1; kw <= 1; kw++) {
        int cc2 = col + kw;
        bool ok = rok && (cc2 >= 0) && (cc2 < 32);
        float tv = ok ? teval : 0.f;
        ull tt = pack2(tv, tv);
        int tp = (kh+1)*3 + (kw+1);
        #pragma unroll
        for (int o2 = 0; o2 < 8; o2++) FMA2(acc[px][o2], tt, w0s2[tp*8 + o2]);
      }
    }
  }

  const float4* h1b = (const float4*)g_h1 + (size_t)bimg * 16384;

  for (int cc = 0; cc < 8; cc++) {
    __syncthreads();
    #pragma unroll
    for (int j = 0; j < 4; j++) {
      int p = tid + 256*j;
      int r = p >> 5, c = p & 31;
      float4 a = h1b[p*16 + cc*2];
      float4 b = h1b[p*16 + cc*2 + 1];
      int base = (r+1)*34 + (c+1);
      tile[0*1156+base]=a.x; tile[1*1156+base]=a.y; tile[2*1156+base]=a.z; tile[3*1156+base]=a.w;
      tile[4*1156+base]=b.x; tile[5*1156+base]=b.y; tile[6*1156+base]=b.z; tile[7*1156+base]=b.w;
    }
    for (int i = tid; i < 576; i += 256) {
      int ci = i / 72, rem = i % 72, tp = rem >> 3, o2 = rem & 7;
      int cin = cc*8 + ci + 1;
      ws2[i] = pack2(w2[(obase+2*o2)*585 + cin*9 + tp],
                     w2[(obase+2*o2+1)*585 + cin*9 + tp]);
    }
    __syncthreads();

    #pragma unroll 1
    for (int ci = 0; ci < 8; ci++) {
      ull vv[4][9];
      const float* tpl = tile + ci*1156;
      #pragma unroll
      for (int px = 0; px < 4; px++) {
        int r = row0 + px*8;
        #pragma unroll
        for (int kh = 0; kh < 3; kh++)
          #pragma unroll
          for (int kw = 0; kw < 3; kw++) {
            float v = tpl[(r+kh)*34 + col + kw];
            vv[px][kh*3+kw] = pack2(v, v);
          }
      }
      const ulonglong2* wrow = (const ulonglong2*)(ws2 + ci*72);
      #pragma unroll
      for (int o2p = 0; o2p < 4; o2p++) {
        ulonglong2 wp[9];
        #pragma unroll
        for (int tp = 0; tp < 9; tp++) wp[tp] = wrow[tp*4 + o2p];
        #pragma unroll
        for (int px = 0; px < 4; px++)
          #pragma unroll
          for (int tp = 0; tp < 9; tp++) {
            FMA2(acc[px][2*o2p],   vv[px][tp], wp[tp].x);
            FMA2(acc[px][2*o2p+1], vv[px][tp], wp[tp].y);
          }
      }
    }
  }

  #pragma unroll
  for (int px = 0; px < 4; px++) {
    int r = row0 + px*8;
    int pidx = r*32 + col;
    float4* dst = (float4*)(g_h2 + (size_t)(bimg*1024 + pidx)*64 + obase);
    #pragma unroll
    for (int q = 0; q < 4; q++) {
      float2 f0 = unpk(acc[px][2*q]);
      float2 f1 = unpk(acc[px][2*q+1]);
      float4 s;
      s.x = fmaxf(f0.x + b2s[4*q+0], 0.f);
      s.y = fmaxf(f0.y + b2s[4*q+1], 0.f);
      s.z = fmaxf(f1.x + b2s[4*q+2], 0.f);
      s.w = fmaxf(f1.y + b2s[4*q+3], 0.f);
      dst[q] = s;
    }
  }
}

// ---------------- conv3: 1x1 (65->8) -> k[stage]; stage 6 also err partials ----------------
__global__ __launch_bounds__(256) void conv3_kernel(const float* __restrict__ w3,
                                                    const float* __restrict__ b3,
                                                    int stage) {
  __shared__ ull w3s2[256];  // [c][o2] = c*4+o2
  __shared__ ull bias2[4];
  __shared__ float red[256];
  int tid = threadIdx.x;
  float tcur = g_t;
  float dtc  = fminf(g_dt, 1.f - tcur);
  float teval = tcur + c_toff[stage] * dtc;

  {
    int c = tid >> 2, o2 = tid & 3;
    w3s2[tid] = pack2(w3[(2*o2)*65 + 1 + c], w3[(2*o2+1)*65 + 1 + c]);
  }
  if (tid < 4)
    bias2[tid] = pack2(b3[2*tid]   + w3[(2*tid)*65]   * teval,
                       b3[2*tid+1] + w3[(2*tid+1)*65] * teval);
  __syncthreads();

  int idx = blockIdx.x * 256 + tid;
  const float4* h2p = (const float4*)(g_h2 + (size_t)idx * 64);

  ull a0 = bias2[0], a1 = bias2[1], a2 = bias2[2], a3 = bias2[3];
  #pragma unroll
  for (int c4 = 0; c4 < 16; c4++) {
    float4 h = h2p[c4];
    ull hh;
    const ull* w = &w3s2[(c4*4)*4];
    hh = pack2(h.x, h.x);
    FMA2(a0, hh, w[0]);  FMA2(a1, hh, w[1]);  FMA2(a2, hh, w[2]);  FMA2(a3, hh, w[3]);
    hh = pack2(h.y, h.y);
    FMA2(a0, hh, w[4]);  FMA2(a1, hh, w[5]);  FMA2(a2, hh, w[6]);  FMA2(a3, hh, w[7]);
    hh = pack2(h.z, h.z);
    FMA2(a0, hh, w[8]);  FMA2(a1, hh, w[9]);  FMA2(a2, hh, w[10]); FMA2(a3, hh, w[11]);
    hh = pack2(h.w, h.w);
    FMA2(a0, hh, w[12]); FMA2(a1, hh, w[13]); FMA2(a2, hh, w[14]); FMA2(a3, hh, w[15]);
  }

  float2 f0 = unpk(a0), f1 = unpk(a1), f2 = unpk(a2), f3 = unpk(a3);
  float kv[8] = {f0.x, f0.y, f1.x, f1.y, f2.x, f2.y, f3.x, f3.y};
  float4* kd = (float4*)g_k[stage];
  kd[idx*2]   = make_float4(kv[0], kv[1], kv[2], kv[3]);
  kd[idx*2+1] = make_float4(kv[4], kv[5], kv[6], kv[7]);

  if (stage == 6) {
    const float4* yp  = (const float4*)g_y;
    const float4* y5p = (const float4*)g_y5;
    float4 ya = yp[idx*2],  yb = yp[idx*2+1];
    float4 za = y5p[idx*2], zb = y5p[idx*2+1];
    float yv[8]  = {ya.x, ya.y, ya.z, ya.w, yb.x, yb.y, yb.z, yb.w};
    float y5v[8] = {za.x, za.y, za.z, za.w, zb.x, zb.y, zb.z, zb.w};
    float e[8];
    {
      const float4* kj = (const float4*)g_k[0];
      float4 p = kj[idx*2], q = kj[idx*2+1];
      e[0]=E1f*p.x; e[1]=E1f*p.y; e[2]=E1f*p.z; e[3]=E1f*p.w;
      e[4]=E1f*q.x; e[5]=E1f*q.y; e[6]=E1f*q.z; e[7]=E1f*q.w;
    }
    {
      const float4* kj = (const float4*)g_k[2];
      float4 p = kj[idx*2], q = kj[idx*2+1];
      e[0]+=E3f*p.x; e[1]+=E3f*p.y; e[2]+=E3f*p.z; e[3]+=E3f*p.w;
      e[4]+=E3f*q.x; e[5]+=E3f*q.y; e[6]+=E3f*q.z; e[7]+=E3f*q.w;
    }
    {
      const float4* kj = (const float4*)g_k[3];
      float4 p = kj[idx*2], q = kj[idx*2+1];
      e[0]+=E4f*p.x; e[1]+=E4f*p.y; e[2]+=E4f*p.z; e[3]+=E4f*p.w;
      e[4]+=E4f*q.x; e[5]+=E4f*q.y; e[6]+=E4f*q.z; e[7]+=E4f*q.w;
    }
    {
      const float4* kj = (const float4*)g_k[4];
      float4 p = kj[idx*2], q = kj[idx*2+1];
      e[0]+=E5f*p.x; e[1]+=E5f*p.y; e[2]+=E5f*p.z; e[3]+=E5f*p.w;
      e[4]+=E5f*q.x; e[5]+=E5f*q.y; e[6]+=E5f*q.z; e[7]+=E5f*q.w;
    }
    {
      const float4* kj = (const float4*)g_k[5];
      float4 p = kj[idx*2], q = kj[idx*2+1];
      e[0]+=E6f*p.x; e[1]+=E6f*p.y; e[2]+=E6f*p.z; e[3]+=E6f*p.w;
      e[4]+=E6f*q.x; e[5]+=E6f*q.y; e[6]+=E6f*q.z; e[7]+=E6f*q.w;
    }
    float local = 0.f;
    #pragma unroll
    for (int c = 0; c < 8; c++) {
      float err = dtc * (e[c] + E7f*kv[c]);
      float tol = 1e-3f + 1e-3f * fmaxf(fabsf(yv[c]), fabsf(y5v[c]));
      float r = err / tol;
      local += r * r;
    }
    red[tid] = local; __syncthreads();
    for (int s = 128; s > 0; s >>= 1) { if (tid < s) red[tid] += red[tid+s]; __syncthreads(); }
    if (tid == 0) g_partial[blockIdx.x] = red[0];
  }
}

// ---------------- step controller ----------------
__global__ void update_kernel() {
  __shared__ float red[256];
  int tid = threadIdx.x;
  red[tid] = g_partial[tid];
  __syncthreads();
  for (int s = 128; s > 0; s >>= 1) { if (tid < s) red[tid] += red[tid+s]; __syncthreads(); }
  if (tid == 0) {
    float err_norm = sqrtf(red[0] * (1.f / (float)NSTATE));
    float tcur = g_t, dt = g_dt;
    float dtc  = fminf(dt, 1.f - tcur);
    bool done = tcur >= 1.f - 1e-7f;
    bool adv  = (err_norm <= 1.f) && (!done);
    g_accept = adv ? 1 : 0;
    g_t = adv ? (tcur + dtc) : tcur;
    float safe = fmaxf(err_norm, 1e-10f);
    float factor = 0.9f * powf(safe, -0.2f);
    factor = fminf(fmaxf(factor, 0.2f), 10.f);
    g_dt = done ? dt : dtc * factor;
  }
}

// ---------------- final: commit last accept + linear head ----------------
__global__ void commit_kernel() {
  if (g_accept == 0) return;
  int i = blockIdx.x * 256 + threadIdx.x;
  g_y[i] = g_y5[i];
}

__global__ __launch_bounds__(256) void head_kernel(const float* __restrict__ wl,
                                                   const float* __restrict__ bl,
                                                   float* __restrict__ out) {
  __shared__ float ys[8192];   // transposed to [c][px]
  __shared__ float red[256];
  int b = blockIdx.x, tid = threadIdx.x;
  const float* yb = g_y + (size_t)b * 8192;   // [px][c]
  for (int i = tid; i < 8192; i += 256) {
    int px = i >> 3, c = i & 7;
    ys[c*1024 + px] = yb[i];
  }
  __syncthreads();
  for (int o = 0; o < 10; o++) {
    float s = 0.f;
    const float* wo = wl + (size_t)o * 8192;
    for (int i = tid; i < 8192; i += 256) s += wo[i] * ys[i];
    red[tid] = s; __syncthreads();
    for (int st = 128; st > 0; st >>= 1) { if (tid < st) red[tid] += red[tid+st]; __syncthreads(); }
    if (tid == 0) out[b*10 + o] = red[0] + bl[o];
    __syncthreads();
  }
}

// ---------------- launcher ----------------
extern "C" void kernel_launch(void* const* d_in, const int* in_sizes, int n_in,
                              void* d_out, int out_size) {
  const float* x  = (const float*)d_in[0];
  const float* w1 = (const float*)d_in[1];
  const float* b1 = (const float*)d_in[2];
  const float* w2 = (const float*)d_in[3];
  const float* b2 = (const float*)d_in[4];
  const float* w3 = (const float*)d_in[5];
  const float* b3 = (const float*)d_in[6];
  const float* wl = (const float*)d_in[7];
  const float* bl = (const float*)d_in[8];
  float* out = (float*)d_out;

  init_kernel<<<NSTATE/256, 256>>>(x);
  for (int step = 0; step < N_STEPS; step++) {
    for (int s = 0; s < 7; s++) {
      conv1_kernel<<<256, 256>>>(w1, b1, s);     // also commits previous accept at s==0
      conv2_kernel<<<dim3(64, 4), 256>>>(w2, b2, s);
      conv3_kernel<<<256, 256>>>(w3, b3, s);     // stage 6 also emits err partials
    }
    update_kernel<<<1, 256>>>();
  }
  commit_kernel<<<NSTATE/256, 256>>>();          // last step's accept
  head_kernel<<<B_IMG, 256>>>(wl, bl, out);
}

// round 3
// speedup vs baseline: 1.2606x; 1.1010x over previous
#include <cuda_runtime.h>
#include <math.h>

#define B_IMG   64
#define CH      8
#define NPIX    1024
#define NSTATE  (B_IMG*CH*NPIX)     // 524288
#define N_STEPS 24

typedef unsigned long long ull;

__device__ __forceinline__ ull pack2(float lo, float hi) {
  ull r; asm("mov.b64 %0, {%1, %2};" : "=l"(r) : "f"(lo), "f"(hi)); return r;
}
__device__ __forceinline__ float2 unpk(ull v) {
  float2 f; asm("mov.b64 {%0, %1}, %2;" : "=f"(f.x), "=f"(f.y) : "l"(v)); return f;
}
#define FMA2(d,a,b) asm("fma.rn.f32x2 %0, %1, %2, %0;" : "+l"(d) : "l"(a), "l"(b))

__device__ __forceinline__ void cpa16(void* smem_dst, const void* gsrc) {
  unsigned s = (unsigned)__cvta_generic_to_shared(smem_dst);
  asm volatile("cp.async.ca.shared.global [%0], [%1], 16;" :: "r"(s), "l"(gsrc));
}
#define CP_COMMIT() asm volatile("cp.async.commit_group;")
#define CP_WAIT0()  asm volatile("cp.async.wait_group 0;")

// ---------------- device state ----------------
// y,y5,k : [b][px][c] (8 contiguous)
__device__ float g_y[NSTATE];
__device__ float g_y5[NSTATE];
__device__ float g_k[7][NSTATE];
__device__ float g_t, g_dt;
__device__ float g_partial[256];
__device__ int   g_accept;

// packed weights (filled once per launch by prep_kernel)
__device__ ull g_w2p[18432];   // [og4][cc8][ci8][tp9][o2_8]
__device__ ull g_w1s[256];     // [c8][o2_32]
__device__ ull g_w1t[32], g_b1p[32];
__device__ ull g_w3s[256];     // [og4][ci16][o2_4]
__device__ ull g_w3t[4], g_b3p[4];
__device__ ull g_w0s[288];     // [og4][tp9][o2_8]  (conv2 t-channel)
__device__ ull g_b2p[32];      // [og4][o2_8]

__constant__ float c_toff[7] = {0.f, 0.2f, 0.3f, 0.8f, (float)(8.0/9.0), 1.f, 1.f};
__constant__ float c_coef[7][6] = {
  {0,0,0,0,0,0},
  {0.2f,0,0,0,0,0},
  {(float)(3.0/40.0),(float)(9.0/40.0),0,0,0,0},
  {(float)(44.0/45.0),(float)(-56.0/15.0),(float)(32.0/9.0),0,0,0},
  {(float)(19372.0/6561.0),(float)(-25360.0/2187.0),(float)(64448.0/6561.0),(float)(-212.0/729.0),0,0},
  {(float)(9017.0/3168.0),(float)(-355.0/33.0),(float)(46732.0/5247.0),(float)(49.0/176.0),(float)(-5103.0/18656.0),0},
  {(float)(35.0/384.0),0.f,(float)(500.0/1113.0),(float)(125.0/192.0),(float)(-2187.0/6784.0),(float)(11.0/84.0)}
};
#define E1f ((float)(71.0/57600.0))
#define E3f ((float)(-71.0/16695.0))
#define E4f ((float)(71.0/1920.0))
#define E5f ((float)(-17253.0/339200.0))
#define E6f ((float)(22.0/525.0))
#define E7f ((float)(-1.0/40.0))

// ---------------- init ----------------
__global__ void init_kernel(const float* __restrict__ x) {
  int i = blockIdx.x * 256 + threadIdx.x;
  if (i == 0) { g_t = 0.f; g_dt = 0.1f; g_accept = 0; }
  if (i < NSTATE) {
    int c = i & 7, p = (i >> 3) & 1023, b = i >> 13;
    g_y[i] = (c < 3) ? x[b*3*NPIX + c*NPIX + p] : 0.f;
  }
}

// ---------------- weight prep (once per launch) ----------------
__global__ void prep_kernel(const float* __restrict__ w1, const float* __restrict__ b1,
                            const float* __restrict__ w2, const float* __restrict__ b2,
                            const float* __restrict__ w3, const float* __restrict__ b3) {
  int i = blockIdx.x * 256 + threadIdx.x;
  if (i < 18432) {
    int o2 = i & 7, tp = (i >> 3) % 9, rem = i / 72;
    int ci = rem & 7, cc = (rem >> 3) & 7, og = rem >> 6;
    int r = (og*16 + 2*o2)*585 + (cc*8 + ci + 1)*9 + tp;
    g_w2p[i] = pack2(w2[r], w2[r + 585]);
  }
  if (i < 256) {
    int c = i >> 5, o2 = i & 31;
    g_w1s[i] = pack2(w1[(2*o2)*9 + 1 + c], w1[(2*o2+1)*9 + 1 + c]);
  }
  if (i < 32) {
    g_w1t[i] = pack2(w1[(2*i)*9], w1[(2*i+1)*9]);
    g_b1p[i] = pack2(b1[2*i], b1[2*i+1]);
  }
  if (i < 256) {
    int og = i >> 6, ci = (i >> 2) & 15, o2 = i & 3;
    g_w3s[i] = pack2(w3[(2*o2)*65 + 1 + og*16 + ci], w3[(2*o2+1)*65 + 1 + og*16 + ci]);
  }
  if (i < 4) {
    g_w3t[i] = pack2(w3[(2*i)*65], w3[(2*i+1)*65]);
    g_b3p[i] = pack2(b3[2*i], b3[2*i+1]);
  }
  if (i < 288) {
    int og = i / 72, tp = (i >> 3) % 9, o2 = i & 7;
    g_w0s[i] = pack2(w2[(og*16 + 2*o2)*585 + tp], w2[(og*16 + 2*o2 + 1)*585 + tp]);
  }
  if (i < 32) {
    int og = i >> 3, o2 = i & 7;
    g_b2p[i] = pack2(b2[og*16 + 2*o2], b2[og*16 + 2*o2 + 1]);
  }
}

// ---------------- fused stage kernel ----------------
// block = 128 threads, tile = 8 rows x 32 cols of one image.
// smem layout (dynamic):
#define SM_H1   0           // float h1s[64][340]  (10x34 haloed planes)  87040 B
#define SM_WB   87040       // ull wb[2][576]                              9216 B
#define SM_W1   96256       // ull w1s[256]                                2048 B
#define SM_B1   98304       // ull bias1[32]                                256 B
#define SM_W3   98560       // ull w3s[256]                                2048 B
#define SM_W0   100608      // ull w0s[288]                                2304 B
#define SM_B2   102912      // ull b2s[32]                                  256 B
#define SM_RED  103168      // float red[128]                               512 B
#define SMEM_BYTES 103680

__global__ __launch_bounds__(128, 2) void fused_kernel(int stage) {
  extern __shared__ char smraw[];
  float* h1s  = (float*)(smraw + SM_H1);
  ull*   wb   = (ull*)  (smraw + SM_WB);
  ull*   w1s  = (ull*)  (smraw + SM_W1);
  ull*   bias1= (ull*)  (smraw + SM_B1);
  ull*   w3s  = (ull*)  (smraw + SM_W3);
  ull*   w0s  = (ull*)  (smraw + SM_W0);
  ull*   b2s  = (ull*)  (smraw + SM_B2);
  float* red  = (float*)(smraw + SM_RED);

  int tid = threadIdx.x;
  int b = blockIdx.x, tile = blockIdx.y;
  int r0 = tile * 8;

  float tcur = g_t;
  float dtc  = fminf(g_dt, 1.f - tcur);
  float teval = tcur + c_toff[stage] * dtc;
  ull tev2 = pack2(teval, teval);

  // small packed weights -> smem
  for (int i = tid; i < 256; i += 128) w1s[i] = g_w1s[i];
  for (int i = tid; i < 256; i += 128) w3s[i] = g_w3s[i];
  for (int i = tid; i < 288; i += 128) w0s[i] = g_w0s[i];
  if (tid < 32) { ull bb = g_b1p[tid]; FMA2(bb, tev2, g_w1t[tid]); bias1[tid] = bb; }
  if (tid < 32) b2s[tid] = g_b2p[tid];

  // prefetch first conv2 weight chunk while doing conv1
  for (int i = tid; i < 288; i += 128) cpa16(wb + i*2, g_w2p + i*2);
  CP_COMMIT();
  __syncthreads();

  // ---- conv1 phase: fill 10x34 haloed h1 tile ----
  for (int p = tid; p < 340; p += 128) {
    int prow = p / 34, pcol = p - prow*34;
    int gr = r0 - 1 + prow, gc = pcol - 1;
    bool valid = (gr >= 0) && (gr < 32) && (gc >= 0) && (gc < 32);
    if (!valid) {
      #pragma unroll 8
      for (int o = 0; o < 64; o++) h1s[o*340 + p] = 0.f;
    } else {
      int idx = b*1024 + gr*32 + gc;
      const float4* yp = (const float4*)g_y;
      float4 ya = yp[idx*2], yb = yp[idx*2+1];
      float yt[8] = {ya.x, ya.y, ya.z, ya.w, yb.x, yb.y, yb.z, yb.w};
      for (int j = 0; j < stage; j++) {
        float cf = c_coef[stage][j];
        if (cf != 0.f) {
          float a = dtc * cf;
          const float4* kj = (const float4*)g_k[j];
          float4 k0 = kj[idx*2], k1 = kj[idx*2+1];
          yt[0]+=a*k0.x; yt[1]+=a*k0.y; yt[2]+=a*k0.z; yt[3]+=a*k0.w;
          yt[4]+=a*k1.x; yt[5]+=a*k1.y; yt[6]+=a*k1.z; yt[7]+=a*k1.w;
        }
      }
      ull yy[8];
      #pragma unroll
      for (int c8 = 0; c8 < 8; c8++) yy[c8] = pack2(yt[c8], yt[c8]);
      #pragma unroll
      for (int o4 = 0; o4 < 16; o4++) {
        ull a0 = bias1[2*o4], a1 = bias1[2*o4+1];
        #pragma unroll
        for (int c8 = 0; c8 < 8; c8++) {
          FMA2(a0, yy[c8], w1s[c8*32 + 2*o4]);
          FMA2(a1, yy[c8], w1s[c8*32 + 2*o4 + 1]);
        }
        float2 f0 = unpk(a0), f1 = unpk(a1);
        h1s[(4*o4+0)*340 + p] = fmaxf(f0.x, 0.f);
        h1s[(4*o4+1)*340 + p] = fmaxf(f0.y, 0.f);
        h1s[(4*o4+2)*340 + p] = fmaxf(f1.x, 0.f);
        h1s[(4*o4+3)*340 + p] = fmaxf(f1.y, 0.f);
      }
    }
  }
  __syncthreads();

  // ---- main loop: conv2 (3x3, 64->64 by 16-och groups) + fused conv3 ----
  int c  = tid & 31;
  int rb = tid >> 5;              // rows rb and rb+4 within tile

  ull kacc[2][4];
  #pragma unroll
  for (int o2 = 0; o2 < 4; o2++) {
    ull kk = g_b3p[o2]; FMA2(kk, tev2, g_w3t[o2]);
    kacc[0][o2] = kk; kacc[1][o2] = kk;
  }

  int cur = 0;
  #pragma unroll 1
  for (int og = 0; og < 4; og++) {
    ull acc[2][8];
    #pragma unroll
    for (int px = 0; px < 2; px++)
      #pragma unroll
      for (int o2 = 0; o2 < 8; o2++) acc[px][o2] = 0ULL;

    #pragma unroll 1
    for (int cc = 0; cc < 8; cc++) {
      CP_WAIT0();
      __syncthreads();
      int nchunk = og*8 + cc + 1;
      if (nchunk < 32) {
        ull* dst = wb + (cur^1)*576;
        const ull* src = g_w2p + nchunk*576;
        for (int i = tid; i < 288; i += 128) cpa16(dst + i*2, src + i*2);
        CP_COMMIT();
      }
      const ull* wc = wb + cur*576;
      #pragma unroll 1
      for (int ci = 0; ci < 8; ci++) {
        const float* pl = h1s + (cc*8 + ci)*340;
        ull v0[9], v1[9];
        #pragma unroll
        for (int kh = 0; kh < 3; kh++)
          #pragma unroll
          for (int kw = 0; kw < 3; kw++) {
            float a = pl[(rb+kh)*34 + c + kw];
            float d = pl[(rb+4+kh)*34 + c + kw];
            v0[kh*3+kw] = pack2(a, a);
            v1[kh*3+kw] = pack2(d, d);
          }
        const ulonglong2* wr = (const ulonglong2*)(wc + ci*72);
        #pragma unroll
        for (int o2p = 0; o2p < 4; o2p++) {
          ulonglong2 wp[9];
          #pragma unroll
          for (int tp = 0; tp < 9; tp++) wp[tp] = wr[tp*4 + o2p];
          #pragma unroll
          for (int tp = 0; tp < 9; tp++) {
            FMA2(acc[0][2*o2p],   v0[tp], wp[tp].x);
            FMA2(acc[0][2*o2p+1], v0[tp], wp[tp].y);
            FMA2(acc[1][2*o2p],   v1[tp], wp[tp].x);
            FMA2(acc[1][2*o2p+1], v1[tp], wp[tp].y);
          }
        }
      }
      cur ^= 1;
    }

    // ---- og epilogue: t-channel + bias + relu -> conv3 partial ----
    #pragma unroll
    for (int px = 0; px < 2; px++) {
      int gr = r0 + rb + px*4, gc = c;
      #pragma unroll
      for (int tp = 0; tp < 9; tp++) {
        int kh = tp / 3, kw = tp - kh*3;
        bool ok = !((kh==0 && gr==0) || (kh==2 && gr==31) ||
                    (kw==0 && gc==0) || (kw==2 && gc==31));
        if (ok) {
          #pragma unroll
          for (int o2 = 0; o2 < 8; o2++)
            FMA2(acc[px][o2], tev2, w0s[og*72 + tp*8 + o2]);
        }
      }
      float h[16];
      #pragma unroll
      for (int q = 0; q < 8; q++) {
        float2 bb = unpk(b2s[og*8 + q]);
        float2 f  = unpk(acc[px][q]);
        h[2*q]   = fmaxf(f.x + bb.x, 0.f);
        h[2*q+1] = fmaxf(f.y + bb.y, 0.f);
      }
      #pragma unroll
      for (int ci = 0; ci < 16; ci++) {
        ull hh = pack2(h[ci], h[ci]);
        const ull* w3r = w3s + og*64 + ci*4;
        FMA2(kacc[px][0], hh, w3r[0]);
        FMA2(kacc[px][1], hh, w3r[1]);
        FMA2(kacc[px][2], hh, w3r[2]);
        FMA2(kacc[px][3], hh, w3r[3]);
      }
    }
  }

  // ---- write k; stage 6: y5 + err partials ----
  float local = 0.f;
  float* kd = g_k[stage];
  #pragma unroll
  for (int px = 0; px < 2; px++) {
    int gr = r0 + rb + px*4;
    int idx = b*1024 + gr*32 + c;
    float2 q0 = unpk(kacc[px][0]), q1 = unpk(kacc[px][1]);
    float2 q2 = unpk(kacc[px][2]), q3 = unpk(kacc[px][3]);
    float kv[8] = {q0.x, q0.y, q1.x, q1.y, q2.x, q2.y, q3.x, q3.y};
    float4* kp = (float4*)kd;
    kp[idx*2]   = make_float4(kv[0], kv[1], kv[2], kv[3]);
    kp[idx*2+1] = make_float4(kv[4], kv[5], kv[6], kv[7]);

    if (stage == 6) {
      const float4* yp = (const float4*)g_y;
      float4 ya = yp[idx*2], yb = yp[idx*2+1];
      float yv[8] = {ya.x, ya.y, ya.z, ya.w, yb.x, yb.y, yb.z, yb.w};
      float yt[8], e[8];
      #pragma unroll
      for (int c8 = 0; c8 < 8; c8++) { yt[c8] = yv[c8]; e[c8] = E7f * kv[c8]; }
      const int   jidx[5] = {0, 2, 3, 4, 5};
      const float bcf[5]  = {(float)(35.0/384.0), (float)(500.0/1113.0),
                             (float)(125.0/192.0), (float)(-2187.0/6784.0),
                             (float)(11.0/84.0)};
      const float ecf[5]  = {E1f, E3f, E4f, E5f, E6f};
      #pragma unroll
      for (int j = 0; j < 5; j++) {
        const float4* kj = (const float4*)g_k[jidx[j]];
        float4 k0 = kj[idx*2], k1 = kj[idx*2+1];
        float kk[8] = {k0.x, k0.y, k0.z, k0.w, k1.x, k1.y, k1.z, k1.w};
        float a = dtc * bcf[j];
        #pragma unroll
        for (int c8 = 0; c8 < 8; c8++) { yt[c8] += a * kk[c8]; e[c8] += ecf[j] * kk[c8]; }
      }
      float4* y5p = (float4*)g_y5;
      y5p[idx*2]   = make_float4(yt[0], yt[1], yt[2], yt[3]);
      y5p[idx*2+1] = make_float4(yt[4], yt[5], yt[6], yt[7]);
      #pragma unroll
      for (int c8 = 0; c8 < 8; c8++) {
        float err = dtc * e[c8];
        float tol = 1e-3f + 1e-3f * fmaxf(fabsf(yv[c8]), fabsf(yt[c8]));
        float r = err / tol;
        local += r * r;
      }
    }
  }

  if (stage == 6) {
    red[tid] = local; __syncthreads();
    for (int s = 64; s > 0; s >>= 1) { if (tid < s) red[tid] += red[tid+s]; __syncthreads(); }
    if (tid == 0) g_partial[tile*64 + b] = red[0];
  }
}

// ---------------- step controller ----------------
__global__ void update_kernel() {
  __shared__ float red[256];
  int tid = threadIdx.x;
  red[tid] = g_partial[tid];
  __syncthreads();
  for (int s = 128; s > 0; s >>= 1) { if (tid < s) red[tid] += red[tid+s]; __syncthreads(); }
  if (tid == 0) {
    float err_norm = sqrtf(red[0] * (1.f / (float)NSTATE));
    float tcur = g_t, dt = g_dt;
    float dtc  = fminf(dt, 1.f - tcur);
    bool done = tcur >= 1.f - 1e-7f;
    bool adv  = (err_norm <= 1.f) && (!done);
    g_accept = adv ? 1 : 0;
    g_t = adv ? (tcur + dtc) : tcur;
    float safe = fmaxf(err_norm, 1e-10f);
    float factor = 0.9f * powf(safe, -0.2f);
    factor = fminf(fmaxf(factor, 0.2f), 10.f);
    g_dt = done ? dt : dtc * factor;
  }
}

__global__ void commit_kernel() {
  if (g_accept == 0) return;
  int i = blockIdx.x * 256 + threadIdx.x;
  g_y[i] = g_y5[i];
}

// ---------------- final linear head ----------------
__global__ __launch_bounds__(256) void head_kernel(const float* __restrict__ wl,
                                                   const float* __restrict__ bl,
                                                   float* __restrict__ out) {
  __shared__ float ys[8192];
  __shared__ float red[256];
  int b = blockIdx.x, tid = threadIdx.x;
  const float* yb = g_y + (size_t)b * 8192;
  for (int i = tid; i < 8192; i += 256) {
    int px = i >> 3, c = i & 7;
    ys[c*1024 + px] = yb[i];
  }
  __syncthreads();
  for (int o = 0; o < 10; o++) {
    float s = 0.f;
    const float* wo = wl + (size_t)o * 8192;
    for (int i = tid; i < 8192; i += 256) s += wo[i] * ys[i];
    red[tid] = s; __syncthreads();
    for (int st = 128; st > 0; st >>= 1) { if (tid < st) red[tid] += red[tid+st]; __syncthreads(); }
    if (tid == 0) out[b*10 + o] = red[0] + bl[o];
    __syncthreads();
  }
}

// ---------------- launcher ----------------
extern "C" void kernel_launch(void* const* d_in, const int* in_sizes, int n_in,
                              void* d_out, int out_size) {
  const float* x  = (const float*)d_in[0];
  const float* w1 = (const float*)d_in[1];
  const float* b1 = (const float*)d_in[2];
  const float* w2 = (const float*)d_in[3];
  const float* b2 = (const float*)d_in[4];
  const float* w3 = (const float*)d_in[5];
  const float* b3 = (const float*)d_in[6];
  const float* wl = (const float*)d_in[7];
  const float* bl = (const float*)d_in[8];
  float* out = (float*)d_out;

  cudaFuncSetAttribute(fused_kernel, cudaFuncAttributeMaxDynamicSharedMemorySize, SMEM_BYTES);

  init_kernel<<<NSTATE/256, 256>>>(x);
  prep_kernel<<<72, 256>>>(w1, b1, w2, b2, w3, b3);
  for (int step = 0; step < N_STEPS; step++) {
    commit_kernel<<<NSTATE/256, 256>>>();
    for (int s = 0; s < 7; s++)
      fused_kernel<<<dim3(B_IMG, 4), 128, SMEM_BYTES>>>(s);
    update_kernel<<<1, 256>>>();
  }
  commit_kernel<<<NSTATE/256, 256>>>();
  head_kernel<<<B_IMG, 256>>>(wl, bl, out);
}